// round 7
// baseline (speedup 1.0000x reference)
#include <cuda_runtime.h>
#include <cuda_bf16.h>

// Problem constants
#define NB 256
#define NL 32
#define ND 512
#define NH 512
#define NH5 2560                      // 5*H rows per weight half
#define NPROJ (2 * NH5)               // 5120 rows of g_WCAT (Wl then Wr)
#define NSLOT 63                      // 32 leaves + 31 internal nodes per batch
#define SCALE_H 0.044194173824159216f // 1/sqrt(512)

// ---------------- device scratch (allocation-free) ----------------
__device__ float g_H[(size_t)NB * NSLOT * NH];        // node h
__device__ float g_C[(size_t)NB * NSLOT * NH];        // node c
__device__ float g_PL[(size_t)NB * NSLOT * NH5];      // W_comp[:,:512] @ h
__device__ float g_PR[(size_t)NB * NSLOT * NH5];      // W_comp[:,512:] @ h
__device__ float g_WCAT[(size_t)NPROJ * NH];          // [Wl; Wr] as 5120 x 512 row-major
__device__ int   g_SEQ[NB * NL];                      // node id at each sequence position
__device__ float g_LOGIT[NB * NL];                    // cached pair logits (by position)
__device__ int   g_KSEL[NB];                          // selected pair per batch (-1 = frozen)

// ---------------- activations (accurate: match fp32 reference to ~2ulp) ----------
__device__ __forceinline__ float sigf(float x) { return 1.0f / (1.0f + expf(-x)); }

// TreeLSTM compose of nodes (nl, nr) of batch b at dim d, from cached projections.
__device__ __forceinline__ void pair_hc(int b, int nl, int nr, int d,
                                        const float* __restrict__ bc,
                                        float& h, float& cn) {
    const float* pl = g_PL + ((size_t)b * NSLOT + nl) * NH5;
    const float* pr = g_PR + ((size_t)b * NSLOT + nr) * NH5;
    float iv = pl[d]        + pr[d]        + bc[d];
    float fl = pl[d + 512]  + pr[d + 512]  + bc[d + 512];
    float fr = pl[d + 1024] + pr[d + 1024] + bc[d + 1024];
    float uu = pl[d + 1536] + pr[d + 1536] + bc[d + 1536];
    float oo = pl[d + 2048] + pr[d + 2048] + bc[d + 2048];
    float cl = g_C[((size_t)b * NSLOT + nl) * NH + d];
    float cr = g_C[((size_t)b * NSLOT + nr) * NH + d];
    cn = cl * sigf(fl + 1.0f) + cr * sigf(fr + 1.0f) + tanhf(uu) * sigf(iv);
    h  = sigf(oo) * tanhf(cn);
}

// ---------------- GEMM: out[m][n] = sum_k Arow(m)[k] * Wrow(n)[k] (+bias) --------
// MODE 0: word  (A = x, W = W_word param (device ptr!), out -> leaf g_H/g_C, +b_word)
// MODE 1: proj of 8192 leaves   (A rows = leaf h, W = g_WCAT, out -> g_PL/g_PR)
// MODE 2: proj of 256 new nodes (A rows = slot 32+iter per batch)
// NOTE: g_WCAT is referenced from DEVICE code only — passing the __device__ symbol
// as a host-side kernel argument passes the host shadow address (silently readable
// as zeros on GB300 via ATS). That was the R2/R3 bug.
template<int MODE>
__device__ __forceinline__ const float* arow(const float* A, int m, int iter) {
    if constexpr (MODE == 0) return A + (size_t)m * ND;
    else if constexpr (MODE == 1) return g_H + ((size_t)(m >> 5) * NSLOT + (m & 31)) * NH;
    else return g_H + ((size_t)m * NSLOT + 32 + iter) * NH;
}

template<int MODE>
__device__ __forceinline__ void store_one(int m, int n, float v, int iter,
                                          const float* __restrict__ bias) {
    if constexpr (MODE == 0) {
        v += bias[n];
        size_t slot = (size_t)(m >> 5) * NSLOT + (m & 31);
        if (n < NH) g_H[slot * NH + n] = v;
        else        g_C[slot * NH + (n - NH)] = v;
    } else {
        size_t slot = (MODE == 1) ? ((size_t)(m >> 5) * NSLOT + (m & 31))
                                  : ((size_t)m * NSLOT + 32 + iter);
        if (n < NH5) g_PL[slot * NH5 + n] = v;
        else         g_PR[slot * NH5 + (n - NH5)] = v;
    }
}

// 128(M) x 64(N) x 16(K) tile, 256 threads, 8x4 per thread. All dims divide exactly.
template<int MODE>
__global__ void __launch_bounds__(256)
gemm_kernel(const float* __restrict__ A, const float* __restrict__ Wparam,
            const float* __restrict__ bias, int iter) {
    const float* __restrict__ W = (MODE == 0) ? Wparam : g_WCAT;  // device-side symbol

    __shared__ float As[16][132];  // [k][m], padded
    __shared__ float Bs[16][68];   // [k][n], padded

    const int t  = threadIdx.x;
    const int ty = t >> 4;         // 0..15 -> 8 m-rows each
    const int tx = t & 15;         // 0..15 -> 4 n-cols each
    const int mBase = blockIdx.y * 128;
    const int nBase = blockIdx.x * 64;

    const int lrow = t >> 2;       // 0..63
    const int kq   = (t & 3) * 4;  // k offset of this thread's float4

    float acc[8][4];
#pragma unroll
    for (int i = 0; i < 8; i++)
#pragma unroll
        for (int j = 0; j < 4; j++) acc[i][j] = 0.0f;

    for (int k0 = 0; k0 < ND; k0 += 16) {
        // load A tile: 128 rows x 16 k (2 float4 per thread)
#pragma unroll
        for (int half = 0; half < 2; half++) {
            int r = lrow + half * 64;
            const float* ap = arow<MODE>(A, mBase + r, iter);
            float4 av = *(const float4*)(ap + k0 + kq);
            As[kq + 0][r] = av.x; As[kq + 1][r] = av.y;
            As[kq + 2][r] = av.z; As[kq + 3][r] = av.w;
        }
        // load B tile: 64 n-rows x 16 k (1 float4 per thread)
        {
            float4 bv = *(const float4*)(W + (size_t)(nBase + lrow) * ND + k0 + kq);
            Bs[kq + 0][lrow] = bv.x; Bs[kq + 1][lrow] = bv.y;
            Bs[kq + 2][lrow] = bv.z; Bs[kq + 3][lrow] = bv.w;
        }
        __syncthreads();
#pragma unroll
        for (int kk = 0; kk < 16; kk++) {
            float4 a0 = *(const float4*)&As[kk][ty * 8];
            float4 a1 = *(const float4*)&As[kk][ty * 8 + 4];
            float4 bq = *(const float4*)&Bs[kk][tx * 4];
            float am[8] = {a0.x, a0.y, a0.z, a0.w, a1.x, a1.y, a1.z, a1.w};
            float bn[4] = {bq.x, bq.y, bq.z, bq.w};
#pragma unroll
            for (int i = 0; i < 8; i++)
#pragma unroll
                for (int j = 0; j < 4; j++) acc[i][j] = fmaf(am[i], bn[j], acc[i][j]);
        }
        __syncthreads();
    }
#pragma unroll
    for (int i = 0; i < 8; i++) {
        int m = mBase + ty * 8 + i;
#pragma unroll
        for (int j = 0; j < 4; j++)
            store_one<MODE>(m, nBase + tx * 4 + j, acc[i][j], iter, bias);
    }
}

// ---------------- small kernels ----------------
__global__ void prep_wcat_kernel(const float* __restrict__ W_comp) {
    int n = blockIdx.x;            // 0..5119
    int d = threadIdx.x;           // 0..511
    float v = (n < NH5) ? W_comp[(size_t)n * (2 * NH) + d]
                        : W_comp[(size_t)(n - NH5) * (2 * NH) + NH + d];
    g_WCAT[(size_t)n * NH + d] = v;
}

__global__ void seq_init_kernel() {
    g_SEQ[blockIdx.x * NL + threadIdx.x] = threadIdx.x;
}

// 256-thread dot-reduce of q[d]*h(pair) over d=0..511
__device__ __forceinline__ float logit_for(int b, int nl, int nr,
                                           const float* __restrict__ bc,
                                           const float* __restrict__ q) {
    float s = 0.0f;
    for (int d = threadIdx.x; d < NH; d += 256) {
        float h, c;
        pair_hc(b, nl, nr, d, bc, h, c);
        s += q[d] * h;
    }
#pragma unroll
    for (int off = 16; off > 0; off >>= 1) s += __shfl_down_sync(0xffffffffu, s, off);
    __shared__ float red[8];
    if ((threadIdx.x & 31) == 0) red[threadIdx.x >> 5] = s;
    __syncthreads();
    float tot = 0.0f;
    if (threadIdx.x == 0) {
#pragma unroll
        for (int w = 0; w < 8; w++) tot += red[w];
    }
    return tot;
}

__global__ void logit_init_kernel(const float* __restrict__ bc, const float* __restrict__ q) {
    int b = blockIdx.x, n = blockIdx.y;   // pair n = (leaf n, leaf n+1)
    float tot = logit_for(b, n, n + 1, bc, q);
    if (threadIdx.x == 0) g_LOGIT[b * NL + n] = tot * SCALE_H;
}

__global__ void select_kernel(const int* __restrict__ length, int iter) {
    int b = threadIdx.x;
    int nv = length[b] - iter - 1;        // allowed pairs: n < nv
    int k = -1;
    if (nv >= 1) {
        float best = g_LOGIT[b * NL + 0];
        k = 0;
        for (int n = 1; n < nv; n++) {
            float v = g_LOGIT[b * NL + n];
            if (v > best) { best = v; k = n; }   // strict > = first-max (jnp.argmax)
        }
    }
    g_KSEL[b] = k;
}

// compose winner into slot 32+iter, then shift seq + logits left past k
__global__ void merge_kernel(const float* __restrict__ bc, int iter) {
    int b = blockIdx.x;
    int k = g_KSEL[b];
    if (k < 0) return;                    // block-uniform: safe before barriers
    int nl = g_SEQ[b * NL + k], nr = g_SEQ[b * NL + k + 1];
    int newnode = 32 + iter;
    int d = threadIdx.x;                  // 512 threads
    float h, c;
    pair_hc(b, nl, nr, d, bc, h, c);
    size_t slot = (size_t)b * NSLOT + newnode;
    g_H[slot * NH + d] = h;
    g_C[slot * NH + d] = c;
    __syncthreads();                      // all warps done reading g_SEQ[k],g_SEQ[k+1]
    if (threadIdx.x < 32) {
        int j = threadIdx.x;
        int m = NL - iter;                // current sequence length
        bool doSeq = (j >= k + 1 && j <= m - 2);
        bool doLog = (j >= k + 1 && j <= m - 3);
        int   sv = doSeq ? g_SEQ[b * NL + j + 1]   : 0;
        float lv = doLog ? g_LOGIT[b * NL + j + 1] : 0.0f;
        __syncwarp();
        if (doSeq) g_SEQ[b * NL + j]   = sv;
        if (doLog) g_LOGIT[b * NL + j] = lv;
        if (j == 0) g_SEQ[b * NL + k] = newnode;
    }
}

// recompute logits at positions k-1 and k (pairs touching the new node)
__global__ void refresh_kernel(const float* __restrict__ bc, const float* __restrict__ q,
                               int iter) {
    int b = blockIdx.x;
    int k = g_KSEL[b];
    if (k < 0) return;                    // block-uniform
    int p = k - 1 + (int)blockIdx.y;
    int npairs = NL - iter - 2;           // pair count after this merge
    if (p < 0 || p >= npairs) return;     // block-uniform
    int nl = g_SEQ[b * NL + p], nr = g_SEQ[b * NL + p + 1];  // post-shift seq
    float tot = logit_for(b, nl, nr, bc, q);
    if (threadIdx.x == 0) g_LOGIT[b * NL + p] = tot * SCALE_H;
}

__global__ void output_kernel(float* __restrict__ out) {
    int b = blockIdx.x;
    int d = threadIdx.x;
    int root = g_SEQ[b * NL + 0];
    out[(size_t)b * NH + d] = g_H[((size_t)b * NSLOT + root) * NH + d];
}

// ---------------- launch ----------------
extern "C" void kernel_launch(void* const* d_in, const int* in_sizes, int n_in,
                              void* d_out, int out_size) {
    const float* x       = (const float*)d_in[0];
    const int*   length  = (const int*)  d_in[1];
    const float* W_word  = (const float*)d_in[2];
    const float* b_word  = (const float*)d_in[3];
    const float* W_comp  = (const float*)d_in[4];
    const float* b_comp  = (const float*)d_in[5];
    const float* c_query = (const float*)d_in[6];
    float* out = (float*)d_out;

    prep_wcat_kernel<<<NPROJ, NH>>>(W_comp);
    seq_init_kernel<<<NB, NL>>>();

    // word GEMM: M=8192, N=1024 (W passed as param: real device pointer)
    gemm_kernel<0><<<dim3(1024 / 64, 8192 / 128), 256>>>(x, W_word, b_word, 0);
    // leaf projections: M=8192, N=5120 (W = g_WCAT resolved inside kernel)
    gemm_kernel<1><<<dim3(NPROJ / 64, 8192 / 128), 256>>>(nullptr, nullptr, nullptr, 0);
    // initial pair logits: 31 pairs per batch
    logit_init_kernel<<<dim3(NB, NL - 1), 256>>>(b_comp, c_query);

    for (int i = 0; i < NL - 1; i++) {
        select_kernel<<<1, NB>>>(length, i);
        merge_kernel<<<NB, NH>>>(b_comp, i);
        // projections of the 256 new nodes: M=256, N=5120
        gemm_kernel<2><<<dim3(NPROJ / 64, 256 / 128), 256>>>(nullptr, nullptr, nullptr, i);
        if (i < NL - 2)
            refresh_kernel<<<dim3(NB, 2), 256>>>(b_comp, c_query, i);
    }
    output_kernel<<<NB, NH>>>(out);
}

// round 8
// speedup vs baseline: 1.0848x; 1.0848x over previous
#include <cuda_runtime.h>
#include <cuda_bf16.h>

// Problem constants
#define NB 256
#define NL 32
#define ND 512
#define NH 512
#define NH5 2560                      // 5*H rows per weight half
#define NPROJ (2 * NH5)               // 5120 rows of g_WCAT (Wl then Wr)
#define NSLOT 63                      // 32 leaves + 31 internal nodes per batch
#define SCALE_H 0.044194173824159216f // 1/sqrt(512)

// ---------------- device scratch (allocation-free) ----------------
__device__ float g_H[(size_t)NB * NSLOT * NH];        // node h
__device__ float g_C[(size_t)NB * NSLOT * NH];        // node c
__device__ float g_PL[(size_t)NB * NSLOT * NH5];      // W_comp[:,:512] @ h
__device__ float g_PR[(size_t)NB * NSLOT * NH5];      // W_comp[:,512:] @ h
__device__ float g_WCAT[(size_t)NPROJ * NH];          // [Wl; Wr] as 5120 x 512 row-major
__device__ int   g_SEQ[NB * NL];                      // node id at each sequence position
__device__ float g_LOGIT[NB * NL];                    // cached pair logits (by position)
__device__ int   g_KSEL[NB];                          // selected pair per batch (-1 = frozen)

// ---------------- activations ----------------
__device__ __forceinline__ float sigf(float x) { return 1.0f / (1.0f + expf(-x)); }

// TreeLSTM compose of nodes (nl, nr) of batch b at dim d, from cached projections.
__device__ __forceinline__ void pair_hc(int b, int nl, int nr, int d,
                                        const float* __restrict__ bc,
                                        float& h, float& cn) {
    const float* pl = g_PL + ((size_t)b * NSLOT + nl) * NH5;
    const float* pr = g_PR + ((size_t)b * NSLOT + nr) * NH5;
    float iv = pl[d]        + pr[d]        + bc[d];
    float fl = pl[d + 512]  + pr[d + 512]  + bc[d + 512];
    float fr = pl[d + 1024] + pr[d + 1024] + bc[d + 1024];
    float uu = pl[d + 1536] + pr[d + 1536] + bc[d + 1536];
    float oo = pl[d + 2048] + pr[d + 2048] + bc[d + 2048];
    float cl = g_C[((size_t)b * NSLOT + nl) * NH + d];
    float cr = g_C[((size_t)b * NSLOT + nr) * NH + d];
    cn = cl * sigf(fl + 1.0f) + cr * sigf(fr + 1.0f) + tanhf(uu) * sigf(iv);
    h  = sigf(oo) * tanhf(cn);
}

// ---------------- GEMM helpers (shared by both tile shapes) ----------------
// MODE 0: word  (A = x, W = W_word param, out -> leaf g_H/g_C, +b_word)
// MODE 1: proj of 8192 leaves   (A rows = leaf h, W = g_WCAT, out -> g_PL/g_PR)
// MODE 2: proj of 256 new nodes (A rows = slot 32+iter per batch)
// g_WCAT is resolved INSIDE device code (host-side __device__ symbol = shadow addr).
template<int MODE>
__device__ __forceinline__ const float* arow(const float* A, int m, int iter) {
    if constexpr (MODE == 0) return A + (size_t)m * ND;
    else if constexpr (MODE == 1) return g_H + ((size_t)(m >> 5) * NSLOT + (m & 31)) * NH;
    else return g_H + ((size_t)m * NSLOT + 32 + iter) * NH;
}

template<int MODE>
__device__ __forceinline__ void store_one(int m, int n, float v, int iter,
                                          const float* __restrict__ bias) {
    if constexpr (MODE == 0) {
        v += bias[n];
        size_t slot = (size_t)(m >> 5) * NSLOT + (m & 31);
        if (n < NH) g_H[slot * NH + n] = v;
        else        g_C[slot * NH + (n - NH)] = v;
    } else {
        size_t slot = (MODE == 1) ? ((size_t)(m >> 5) * NSLOT + (m & 31))
                                  : ((size_t)m * NSLOT + 32 + iter);
        if (n < NH5) g_PL[slot * NH5 + n] = v;
        else         g_PR[slot * NH5 + (n - NH5)] = v;
    }
}

// ---- 128(M) x 128(N) x 16(K) tile, 256 threads, 8x8 per thread (modes 0/1) ----
template<int MODE>
__global__ void __launch_bounds__(256, 2)
gemm128_kernel(const float* __restrict__ A, const float* __restrict__ Wparam,
               const float* __restrict__ bias, int iter) {
    const float* __restrict__ W = (MODE == 0) ? Wparam : g_WCAT;

    __shared__ float As[16][132];
    __shared__ float Bs[16][132];

    const int t  = threadIdx.x;
    const int ty = t >> 4;           // 0..15 -> 8 m-rows
    const int tx = t & 15;           // 0..15 -> 8 n-cols
    const int mBase = blockIdx.y * 128;
    const int nBase = blockIdx.x * 128;

    const int lrow = t >> 2;         // 0..63
    const int kq   = (t & 3) * 4;    // k offset of this thread's float4

    float acc[8][8];
#pragma unroll
    for (int i = 0; i < 8; i++)
#pragma unroll
        for (int j = 0; j < 8; j++) acc[i][j] = 0.0f;

    for (int k0 = 0; k0 < ND; k0 += 16) {
#pragma unroll
        for (int half = 0; half < 2; half++) {
            int r = lrow + half * 64;
            const float* ap = arow<MODE>(A, mBase + r, iter);
            float4 av = *(const float4*)(ap + k0 + kq);
            As[kq + 0][r] = av.x; As[kq + 1][r] = av.y;
            As[kq + 2][r] = av.z; As[kq + 3][r] = av.w;
            float4 bv = *(const float4*)(W + (size_t)(nBase + r) * ND + k0 + kq);
            Bs[kq + 0][r] = bv.x; Bs[kq + 1][r] = bv.y;
            Bs[kq + 2][r] = bv.z; Bs[kq + 3][r] = bv.w;
        }
        __syncthreads();
#pragma unroll
        for (int kk = 0; kk < 16; kk++) {
            float4 a0 = *(const float4*)&As[kk][ty * 8];
            float4 a1 = *(const float4*)&As[kk][ty * 8 + 4];
            float4 b0 = *(const float4*)&Bs[kk][tx * 8];
            float4 b1 = *(const float4*)&Bs[kk][tx * 8 + 4];
            float am[8] = {a0.x, a0.y, a0.z, a0.w, a1.x, a1.y, a1.z, a1.w};
            float bn[8] = {b0.x, b0.y, b0.z, b0.w, b1.x, b1.y, b1.z, b1.w};
#pragma unroll
            for (int i = 0; i < 8; i++)
#pragma unroll
                for (int j = 0; j < 8; j++) acc[i][j] = fmaf(am[i], bn[j], acc[i][j]);
        }
        __syncthreads();
    }
#pragma unroll
    for (int i = 0; i < 8; i++) {
        int m = mBase + ty * 8 + i;
#pragma unroll
        for (int j = 0; j < 8; j++)
            store_one<MODE>(m, nBase + tx * 8 + j, acc[i][j], iter, bias);
    }
}

// ---- 64(M) x 64(N) x 16(K) tile, 256 threads, 4x4 per thread (mode 2, M=256) ----
__global__ void __launch_bounds__(256)
gemm64_kernel(int iter) {
    const float* __restrict__ W = g_WCAT;

    __shared__ float As[16][68];
    __shared__ float Bs[16][68];

    const int t  = threadIdx.x;
    const int ty = t >> 4;           // 0..15 -> 4 m-rows
    const int tx = t & 15;           // 0..15 -> 4 n-cols
    const int mBase = blockIdx.y * 64;
    const int nBase = blockIdx.x * 64;

    const int lrow = t >> 2;         // 0..63
    const int kq   = (t & 3) * 4;

    float acc[4][4];
#pragma unroll
    for (int i = 0; i < 4; i++)
#pragma unroll
        for (int j = 0; j < 4; j++) acc[i][j] = 0.0f;

    for (int k0 = 0; k0 < ND; k0 += 16) {
        {
            const float* ap = arow<2>(nullptr, mBase + lrow, iter);
            float4 av = *(const float4*)(ap + k0 + kq);
            As[kq + 0][lrow] = av.x; As[kq + 1][lrow] = av.y;
            As[kq + 2][lrow] = av.z; As[kq + 3][lrow] = av.w;
            float4 bv = *(const float4*)(W + (size_t)(nBase + lrow) * ND + k0 + kq);
            Bs[kq + 0][lrow] = bv.x; Bs[kq + 1][lrow] = bv.y;
            Bs[kq + 2][lrow] = bv.z; Bs[kq + 3][lrow] = bv.w;
        }
        __syncthreads();
#pragma unroll
        for (int kk = 0; kk < 16; kk++) {
            float4 a4 = *(const float4*)&As[kk][ty * 4];
            float4 b4 = *(const float4*)&Bs[kk][tx * 4];
            float am[4] = {a4.x, a4.y, a4.z, a4.w};
            float bn[4] = {b4.x, b4.y, b4.z, b4.w};
#pragma unroll
            for (int i = 0; i < 4; i++)
#pragma unroll
                for (int j = 0; j < 4; j++) acc[i][j] = fmaf(am[i], bn[j], acc[i][j]);
        }
        __syncthreads();
    }
#pragma unroll
    for (int i = 0; i < 4; i++) {
        int m = mBase + ty * 4 + i;
#pragma unroll
        for (int j = 0; j < 4; j++)
            store_one<2>(m, nBase + tx * 4 + j, acc[i][j], iter, nullptr);
    }
}

// ---------------- small kernels ----------------
__global__ void prep_wcat_kernel(const float* __restrict__ W_comp) {
    int n = blockIdx.x;
    int d = threadIdx.x;
    float v = (n < NH5) ? W_comp[(size_t)n * (2 * NH) + d]
                        : W_comp[(size_t)(n - NH5) * (2 * NH) + NH + d];
    g_WCAT[(size_t)n * NH + d] = v;
}

__global__ void seq_init_kernel() {
    g_SEQ[blockIdx.x * NL + threadIdx.x] = threadIdx.x;
}

// 256-thread dot-reduce of q[d]*h(pair) over d=0..511
__device__ __forceinline__ float logit_for(int b, int nl, int nr,
                                           const float* __restrict__ bc,
                                           const float* __restrict__ q) {
    float s = 0.0f;
    for (int d = threadIdx.x; d < NH; d += 256) {
        float h, c;
        pair_hc(b, nl, nr, d, bc, h, c);
        s += q[d] * h;
    }
#pragma unroll
    for (int off = 16; off > 0; off >>= 1) s += __shfl_down_sync(0xffffffffu, s, off);
    __shared__ float red[8];
    if ((threadIdx.x & 31) == 0) red[threadIdx.x >> 5] = s;
    __syncthreads();
    float tot = 0.0f;
    if (threadIdx.x == 0) {
#pragma unroll
        for (int w = 0; w < 8; w++) tot += red[w];
    }
    return tot;
}

__global__ void logit_init_kernel(const float* __restrict__ bc, const float* __restrict__ q) {
    int b = blockIdx.x, n = blockIdx.y;
    float tot = logit_for(b, n, n + 1, bc, q);
    if (threadIdx.x == 0) g_LOGIT[b * NL + n] = tot * SCALE_H;
}

// fused select + compose + shift. 512 threads.
__global__ void merge_kernel(const float* __restrict__ bc,
                             const int* __restrict__ length, int iter) {
    int b = blockIdx.x;
    __shared__ int sk, snl, snr;
    if (threadIdx.x < 32) {
        int nv = length[b] - iter - 1;        // allowed pairs: n < nv
        int lane = threadIdx.x;
        float v = (lane < nv) ? g_LOGIT[b * NL + lane] : -3.0e38f;
        int idx = lane;
#pragma unroll
        for (int off = 16; off > 0; off >>= 1) {
            float ov = __shfl_down_sync(0xffffffffu, v, off);
            int   oi = __shfl_down_sync(0xffffffffu, idx, off);
            if (ov > v || (ov == v && oi < idx)) { v = ov; idx = oi; }  // first-max
        }
        if (lane == 0) {
            int k = (nv >= 1) ? idx : -1;
            sk = k;
            g_KSEL[b] = k;
            if (k >= 0) { snl = g_SEQ[b * NL + k]; snr = g_SEQ[b * NL + k + 1]; }
        }
    }
    __syncthreads();
    int k = sk;
    if (k < 0) return;                        // uniform: all threads past barrier
    int nl = snl, nr = snr;
    int newnode = 32 + iter;
    int d = threadIdx.x;
    float h, c;
    pair_hc(b, nl, nr, d, bc, h, c);
    size_t slot = (size_t)b * NSLOT + newnode;
    g_H[slot * NH + d] = h;
    g_C[slot * NH + d] = c;
    // shift seq + logits left past k (warp 0 only; no other warp touches g_SEQ/g_LOGIT)
    if (threadIdx.x < 32) {
        int j = threadIdx.x;
        int m = NL - iter;                    // current sequence length
        bool doSeq = (j >= k + 1 && j <= m - 2);
        bool doLog = (j >= k + 1 && j <= m - 3);
        int   sv = doSeq ? g_SEQ[b * NL + j + 1]   : 0;
        float lv = doLog ? g_LOGIT[b * NL + j + 1] : 0.0f;
        __syncwarp();
        if (doSeq) g_SEQ[b * NL + j]   = sv;
        if (doLog) g_LOGIT[b * NL + j] = lv;
        if (j == 0) g_SEQ[b * NL + k] = newnode;
    }
}

// recompute logits at positions k-1 and k (pairs touching the new node)
__global__ void refresh_kernel(const float* __restrict__ bc, const float* __restrict__ q,
                               int iter) {
    int b = blockIdx.x;
    int k = g_KSEL[b];
    if (k < 0) return;
    int p = k - 1 + (int)blockIdx.y;
    int npairs = NL - iter - 2;
    if (p < 0 || p >= npairs) return;
    int nl = g_SEQ[b * NL + p], nr = g_SEQ[b * NL + p + 1];
    float tot = logit_for(b, nl, nr, bc, q);
    if (threadIdx.x == 0) g_LOGIT[b * NL + p] = tot * SCALE_H;
}

__global__ void output_kernel(float* __restrict__ out) {
    int b = blockIdx.x;
    int d = threadIdx.x;
    int root = g_SEQ[b * NL + 0];
    out[(size_t)b * NH + d] = g_H[((size_t)b * NSLOT + root) * NH + d];
}

// ---------------- launch ----------------
extern "C" void kernel_launch(void* const* d_in, const int* in_sizes, int n_in,
                              void* d_out, int out_size) {
    const float* x       = (const float*)d_in[0];
    const int*   length  = (const int*)  d_in[1];
    const float* W_word  = (const float*)d_in[2];
    const float* b_word  = (const float*)d_in[3];
    const float* W_comp  = (const float*)d_in[4];
    const float* b_comp  = (const float*)d_in[5];
    const float* c_query = (const float*)d_in[6];
    float* out = (float*)d_out;

    prep_wcat_kernel<<<NPROJ, NH>>>(W_comp);
    seq_init_kernel<<<NB, NL>>>();

    // word GEMM: M=8192, N=1024
    gemm128_kernel<0><<<dim3(1024 / 128, 8192 / 128), 256>>>(x, W_word, b_word, 0);
    // leaf projections: M=8192, N=5120
    gemm128_kernel<1><<<dim3(NPROJ / 128, 8192 / 128), 256>>>(nullptr, nullptr, nullptr, 0);
    // initial pair logits
    logit_init_kernel<<<dim3(NB, NL - 1), 256>>>(b_comp, c_query);

    for (int i = 0; i < NL - 1; i++) {
        merge_kernel<<<NB, NH>>>(b_comp, length, i);             // select fused in
        gemm64_kernel<<<dim3(NPROJ / 64, 256 / 64), 256>>>(i);   // 320 CTAs
        if (i < NL - 2)
            refresh_kernel<<<dim3(NB, 2), 256>>>(b_comp, c_query, i);
    }
    output_kernel<<<NB, NH>>>(out);
}

// round 14
// speedup vs baseline: 1.1944x; 1.1010x over previous
#include <cuda_runtime.h>
#include <cuda_bf16.h>

// Problem constants
#define NB 256
#define NL 32
#define ND 512
#define NH 512
#define NH5 2560                      // 5*H rows per weight half
#define NPROJ (2 * NH5)               // 5120 rows of g_WCAT (Wl then Wr)
#define NSLOT 63                      // 32 leaves + 31 internal nodes per batch
#define SCALE_H 0.044194173824159216f // 1/sqrt(512)

// ---------------- device scratch (allocation-free) ----------------
__device__ float g_H[(size_t)NB * NSLOT * NH];        // node h
__device__ float g_C[(size_t)NB * NSLOT * NH];        // node c
__device__ float g_PL[(size_t)NB * NSLOT * NH5];      // W_comp[:,:512] @ h
__device__ float g_PR[(size_t)NB * NSLOT * NH5];      // W_comp[:,512:] @ h
__device__ float g_WCAT[(size_t)NPROJ * NH];          // [Wl; Wr] as 5120 x 512 row-major
__device__ int   g_SEQ[NB * NL];                      // node id at each sequence position
__device__ float g_LOGIT[NB * NL];                    // cached pair logits (by position)
__device__ int   g_KSEL[NB];                          // selected pair per batch (-1 = frozen)

// ---------------- activations ----------------
__device__ __forceinline__ float sigf(float x) { return 1.0f / (1.0f + expf(-x)); }

// TreeLSTM compose of nodes (nl, nr) of batch b at dim d, from cached projections.
__device__ __forceinline__ void pair_hc(int b, int nl, int nr, int d,
                                        const float* __restrict__ bc,
                                        float& h, float& cn) {
    const float* pl = g_PL + ((size_t)b * NSLOT + nl) * NH5;
    const float* pr = g_PR + ((size_t)b * NSLOT + nr) * NH5;
    float iv = pl[d]        + pr[d]        + bc[d];
    float fl = pl[d + 512]  + pr[d + 512]  + bc[d + 512];
    float fr = pl[d + 1024] + pr[d + 1024] + bc[d + 1024];
    float uu = pl[d + 1536] + pr[d + 1536] + bc[d + 1536];
    float oo = pl[d + 2048] + pr[d + 2048] + bc[d + 2048];
    float cl = g_C[((size_t)b * NSLOT + nl) * NH + d];
    float cr = g_C[((size_t)b * NSLOT + nr) * NH + d];
    cn = cl * sigf(fl + 1.0f) + cr * sigf(fr + 1.0f) + tanhf(uu) * sigf(iv);
    h  = sigf(oo) * tanhf(cn);
}

// ---------------- GEMM helpers ----------------
// MODE 0: word  (A = x, W = W_word param, out -> leaf g_H/g_C, +b_word)
// MODE 1: proj of 8192 leaves   (A rows = leaf h, W = g_WCAT, out -> g_PL/g_PR)
// MODE 2: proj of 256 new nodes (A rows = slot 32+iter per batch)
// g_WCAT resolved inside device code only (host-side __device__ symbol = shadow addr).
template<int MODE>
__device__ __forceinline__ const float* arow(const float* A, int m, int iter) {
    if constexpr (MODE == 0) return A + (size_t)m * ND;
    else if constexpr (MODE == 1) return g_H + ((size_t)(m >> 5) * NSLOT + (m & 31)) * NH;
    else return g_H + ((size_t)m * NSLOT + 32 + iter) * NH;
}

template<int MODE>
__device__ __forceinline__ void store_one(int m, int n, float v, int iter,
                                          const float* __restrict__ bias) {
    if constexpr (MODE == 0) {
        v += bias[n];
        size_t slot = (size_t)(m >> 5) * NSLOT + (m & 31);
        if (n < NH) g_H[slot * NH + n] = v;
        else        g_C[slot * NH + (n - NH)] = v;
    } else {
        size_t slot = (MODE == 1) ? ((size_t)(m >> 5) * NSLOT + (m & 31))
                                  : ((size_t)m * NSLOT + 32 + iter);
        if (n < NH5) g_PL[slot * NH5 + n] = v;
        else         g_PR[slot * NH5 + (n - NH5)] = v;
    }
}

// ---- 128(M) x 64(N) x 16(K) tile, 256 threads, 8x4 per thread ----
// Register-staged double buffering: LDG for chunk k0+16 issued before computing
// chunk k0 from smem, hiding DRAM/L2 latency behind 512 FFMAs of compute.
template<int MODE>
__global__ void __launch_bounds__(256, 3)
gemm_kernel(const float* __restrict__ A, const float* __restrict__ Wparam,
            const float* __restrict__ bias, int iter) {
    const float* __restrict__ W = (MODE == 0) ? Wparam : g_WCAT;

    __shared__ float As[16][132];  // [k][m], padded
    __shared__ float Bs[16][68];   // [k][n], padded

    const int t  = threadIdx.x;
    const int ty = t >> 4;         // 0..15 -> 8 m-rows each
    const int tx = t & 15;         // 0..15 -> 4 n-cols each
    const int mBase = blockIdx.y * 128;
    const int nBase = blockIdx.x * 64;

    const int lrow = t >> 2;       // 0..63
    const int kq   = (t & 3) * 4;  // k offset of this thread's float4

    const float* apL = arow<MODE>(A, mBase + lrow, iter);
    const float* apH = arow<MODE>(A, mBase + lrow + 64, iter);
    const float* bp  = W + (size_t)(nBase + lrow) * ND;

    float acc[8][4];
#pragma unroll
    for (int i = 0; i < 8; i++)
#pragma unroll
        for (int j = 0; j < 4; j++) acc[i][j] = 0.0f;

    // prologue: stage chunk 0
    float4 avL = *(const float4*)(apL + kq);
    float4 avH = *(const float4*)(apH + kq);
    float4 bv  = *(const float4*)(bp + kq);

    for (int k0 = 0; k0 < ND; k0 += 16) {
        // commit staged regs -> smem
        As[kq + 0][lrow] = avL.x; As[kq + 1][lrow] = avL.y;
        As[kq + 2][lrow] = avL.z; As[kq + 3][lrow] = avL.w;
        As[kq + 0][lrow + 64] = avH.x; As[kq + 1][lrow + 64] = avH.y;
        As[kq + 2][lrow + 64] = avH.z; As[kq + 3][lrow + 64] = avH.w;
        Bs[kq + 0][lrow] = bv.x; Bs[kq + 1][lrow] = bv.y;
        Bs[kq + 2][lrow] = bv.z; Bs[kq + 3][lrow] = bv.w;
        __syncthreads();

        // prefetch next chunk while computing this one
        if (k0 + 16 < ND) {
            avL = *(const float4*)(apL + k0 + 16 + kq);
            avH = *(const float4*)(apH + k0 + 16 + kq);
            bv  = *(const float4*)(bp  + k0 + 16 + kq);
        }

#pragma unroll
        for (int kk = 0; kk < 16; kk++) {
            float4 a0 = *(const float4*)&As[kk][ty * 8];
            float4 a1 = *(const float4*)&As[kk][ty * 8 + 4];
            float4 bq = *(const float4*)&Bs[kk][tx * 4];
            float am[8] = {a0.x, a0.y, a0.z, a0.w, a1.x, a1.y, a1.z, a1.w};
            float bn[4] = {bq.x, bq.y, bq.z, bq.w};
#pragma unroll
            for (int i = 0; i < 8; i++)
#pragma unroll
                for (int j = 0; j < 4; j++) acc[i][j] = fmaf(am[i], bn[j], acc[i][j]);
        }
        __syncthreads();
    }
#pragma unroll
    for (int i = 0; i < 8; i++) {
        int m = mBase + ty * 8 + i;
#pragma unroll
        for (int j = 0; j < 4; j++)
            store_one<MODE>(m, nBase + tx * 4 + j, acc[i][j], iter, bias);
    }
}

// ---- 64 x 64 x 16 tile, 256 threads, 4x4 per thread (mode 2, M=256), prefetch ----
__global__ void __launch_bounds__(256)
gemm64_kernel(int iter) {
    const float* __restrict__ W = g_WCAT;

    __shared__ float As[16][68];
    __shared__ float Bs[16][68];

    const int t  = threadIdx.x;
    const int ty = t >> 4;
    const int tx = t & 15;
    const int mBase = blockIdx.y * 64;
    const int nBase = blockIdx.x * 64;

    const int lrow = t >> 2;
    const int kq   = (t & 3) * 4;

    const float* ap = arow<2>(nullptr, mBase + lrow, iter);
    const float* bp = W + (size_t)(nBase + lrow) * ND;

    float acc[4][4];
#pragma unroll
    for (int i = 0; i < 4; i++)
#pragma unroll
        for (int j = 0; j < 4; j++) acc[i][j] = 0.0f;

    float4 av = *(const float4*)(ap + kq);
    float4 bv = *(const float4*)(bp + kq);

    for (int k0 = 0; k0 < ND; k0 += 16) {
        As[kq + 0][lrow] = av.x; As[kq + 1][lrow] = av.y;
        As[kq + 2][lrow] = av.z; As[kq + 3][lrow] = av.w;
        Bs[kq + 0][lrow] = bv.x; Bs[kq + 1][lrow] = bv.y;
        Bs[kq + 2][lrow] = bv.z; Bs[kq + 3][lrow] = bv.w;
        __syncthreads();

        if (k0 + 16 < ND) {
            av = *(const float4*)(ap + k0 + 16 + kq);
            bv = *(const float4*)(bp + k0 + 16 + kq);
        }

#pragma unroll
        for (int kk = 0; kk < 16; kk++) {
            float4 a4 = *(const float4*)&As[kk][ty * 4];
            float4 b4 = *(const float4*)&Bs[kk][tx * 4];
            float am[4] = {a4.x, a4.y, a4.z, a4.w};
            float bn[4] = {b4.x, b4.y, b4.z, b4.w};
#pragma unroll
            for (int i = 0; i < 4; i++)
#pragma unroll
                for (int j = 0; j < 4; j++) acc[i][j] = fmaf(am[i], bn[j], acc[i][j]);
        }
        __syncthreads();
    }
#pragma unroll
    for (int i = 0; i < 4; i++) {
        int m = mBase + ty * 4 + i;
#pragma unroll
        for (int j = 0; j < 4; j++)
            store_one<2>(m, nBase + tx * 4 + j, acc[i][j], iter, nullptr);
    }
}

// ---------------- small kernels ----------------
__global__ void prep_wcat_kernel(const float* __restrict__ W_comp) {
    int n = blockIdx.x;
    int d = threadIdx.x;
    float v = (n < NH5) ? W_comp[(size_t)n * (2 * NH) + d]
                        : W_comp[(size_t)(n - NH5) * (2 * NH) + NH + d];
    g_WCAT[(size_t)n * NH + d] = v;
}

__global__ void seq_init_kernel() {
    g_SEQ[blockIdx.x * NL + threadIdx.x] = threadIdx.x;
}

// 256-thread dot-reduce of q[d]*h(pair) over d=0..511 (used by logit_init only)
__device__ __forceinline__ float logit_for(int b, int nl, int nr,
                                           const float* __restrict__ bc,
                                           const float* __restrict__ q) {
    float s = 0.0f;
    for (int d = threadIdx.x; d < NH; d += 256) {
        float h, c;
        pair_hc(b, nl, nr, d, bc, h, c);
        s += q[d] * h;
    }
#pragma unroll
    for (int off = 16; off > 0; off >>= 1) s += __shfl_down_sync(0xffffffffu, s, off);
    __shared__ float red[8];
    if ((threadIdx.x & 31) == 0) red[threadIdx.x >> 5] = s;
    __syncthreads();
    float tot = 0.0f;
    if (threadIdx.x == 0) {
#pragma unroll
        for (int w = 0; w < 8; w++) tot += red[w];
    }
    return tot;
}

__global__ void logit_init_kernel(const float* __restrict__ bc, const float* __restrict__ q) {
    int b = blockIdx.x, n = blockIdx.y;
    float tot = logit_for(b, n, n + 1, bc, q);
    if (threadIdx.x == 0) g_LOGIT[b * NL + n] = tot * SCALE_H;
}

// Fused: refresh (prev iter's dirty logits) + select + compose + shift. 512 threads.
__global__ void merge_kernel(const float* __restrict__ bc, const float* __restrict__ q,
                             const int* __restrict__ length, int iter) {
    int b = blockIdx.x;
    int tid = threadIdx.x;
    __shared__ float red[16];             // 512 threads = 16 warps (R8 bug: was [8])
    __shared__ int sk, snl, snr;

    // ---- folded refresh of previous iteration's decision (iter >= 1) ----
    // Uses g_SEQ/g_LOGIT post-shift from iter-1 and projections of node 32+(iter-1)
    // computed by the gemm64 launched between the two merges.
    if (iter > 0) {
        int pk = g_KSEL[b];               // block-uniform
        if (pk >= 0) {
            int half = tid >> 8;          // 0: position pk-1, 1: position pk
            int lt   = tid & 255;
            int p = pk - 1 + half;
            int npairs = NL - iter - 1;   // = NL - (iter-1) - 2
            bool valid = (p >= 0 && p < npairs);   // uniform within each half
            float s = 0.0f;
            if (valid) {
                int nl = g_SEQ[b * NL + p], nr = g_SEQ[b * NL + p + 1];
                for (int d = lt; d < NH; d += 256) {
                    float h, c;
                    pair_hc(b, nl, nr, d, bc, h, c);
                    s += q[d] * h;
                }
            }
#pragma unroll
            for (int off = 16; off > 0; off >>= 1) s += __shfl_down_sync(0xffffffffu, s, off);
            if ((tid & 31) == 0) red[tid >> 5] = s;
            __syncthreads();
            if (lt == 0 && valid) {
                // half g spans warps 8g .. 8g+7 (256 threads = 8 warps)
                float tot = 0.0f;
#pragma unroll
                for (int w = 0; w < 8; w++) tot += red[half * 8 + w];
                g_LOGIT[b * NL + p] = tot * SCALE_H;
            }
            __syncthreads();              // logits visible to select below
        }
    }

    // ---- select (warp 0): first-max argmax over valid pairs ----
    if (tid < 32) {
        int nv = length[b] - iter - 1;    // allowed pairs: n < nv
        int lane = tid;
        float v = (lane < nv) ? g_LOGIT[b * NL + lane] : -3.0e38f;
        int idx = lane;
#pragma unroll
        for (int off = 16; off > 0; off >>= 1) {
            float ov = __shfl_down_sync(0xffffffffu, v, off);
            int   oi = __shfl_down_sync(0xffffffffu, idx, off);
            if (ov > v || (ov == v && oi < idx)) { v = ov; idx = oi; }  // first-max
        }
        if (lane == 0) {
            int k = (nv >= 1) ? idx : -1;
            sk = k;
            g_KSEL[b] = k;
            if (k >= 0) { snl = g_SEQ[b * NL + k]; snr = g_SEQ[b * NL + k + 1]; }
        }
    }
    __syncthreads();
    int k = sk;
    if (k < 0) return;                    // uniform: all barriers already passed
    int nl = snl, nr = snr;
    int newnode = 32 + iter;
    int d = tid;                          // 512 threads
    float h, c;
    pair_hc(b, nl, nr, d, bc, h, c);
    size_t slot = (size_t)b * NSLOT + newnode;
    g_H[slot * NH + d] = h;
    g_C[slot * NH + d] = c;
    // shift seq + logits left past k (warp 0 only)
    if (tid < 32) {
        int j = tid;
        int m = NL - iter;                // current sequence length
        bool doSeq = (j >= k + 1 && j <= m - 2);
        bool doLog = (j >= k + 1 && j <= m - 3);
        int   sv = doSeq ? g_SEQ[b * NL + j + 1]   : 0;
        float lv = doLog ? g_LOGIT[b * NL + j + 1] : 0.0f;
        __syncwarp();
        if (doSeq) g_SEQ[b * NL + j]   = sv;
        if (doLog) g_LOGIT[b * NL + j] = lv;
        if (j == 0) g_SEQ[b * NL + k] = newnode;
    }
}

__global__ void output_kernel(float* __restrict__ out) {
    int b = blockIdx.x;
    int d = threadIdx.x;
    int root = g_SEQ[b * NL + 0];
    out[(size_t)b * NH + d] = g_H[((size_t)b * NSLOT + root) * NH + d];
}

// ---------------- launch ----------------
extern "C" void kernel_launch(void* const* d_in, const int* in_sizes, int n_in,
                              void* d_out, int out_size) {
    const float* x       = (const float*)d_in[0];
    const int*   length  = (const int*)  d_in[1];
    const float* W_word  = (const float*)d_in[2];
    const float* b_word  = (const float*)d_in[3];
    const float* W_comp  = (const float*)d_in[4];
    const float* b_comp  = (const float*)d_in[5];
    const float* c_query = (const float*)d_in[6];
    float* out = (float*)d_out;

    prep_wcat_kernel<<<NPROJ, NH>>>(W_comp);
    seq_init_kernel<<<NB, NL>>>();

    // word GEMM: M=8192, N=1024
    gemm_kernel<0><<<dim3(1024 / 64, 8192 / 128), 256>>>(x, W_word, b_word, 0);
    // leaf projections: M=8192, N=5120
    gemm_kernel<1><<<dim3(NPROJ / 64, 8192 / 128), 256>>>(nullptr, nullptr, nullptr, 0);
    // initial pair logits
    logit_init_kernel<<<dim3(NB, NL - 1), 256>>>(b_comp, c_query);

    for (int i = 0; i < NL - 1; i++) {
        merge_kernel<<<NB, NH>>>(b_comp, c_query, length, i);    // refresh+select fused
        gemm64_kernel<<<dim3(NPROJ / 64, 256 / 64), 256>>>(i);   // 320 CTAs
    }
    output_kernel<<<NB, NH>>>(out);
}